// round 11
// baseline (speedup 1.0000x reference)
#include <cuda_runtime.h>
#include <math.h>

#define MDIM  2048
#define NHEAD 32
#define HDIM  64
#define BATCH 16
#define SEQT  256
#define SWIN  512
#define MROWS (BATCH*SEQT)          /* 4096 */
#define WN    (MDIM*MDIM)           /* 4194304 */
#define XN    (MROWS*MDIM)          /* 8388608 */

/* ---------------- scratch (static device arrays; no cudaMalloc) ---------- */
__device__ float          g_q   [BATCH*NHEAD*SEQT*HDIM];   /* rope'd Q fp32 */
__device__ float          g_krot[BATCH*NHEAD*SEQT*HDIM];   /* rope'd K fp32 */
__device__ unsigned short g_xhi[XN], g_xlo[XN];            /* X  bf16 split */
__device__ unsigned short g_whi[4u*WN], g_wlo[4u*WN];      /* Wq,Wk,Wv,Wo   */
__device__ unsigned short g_ahi[XN], g_alo[XN];            /* attn out split */
__device__ float          g_cos[SEQT*32], g_sin[SEQT*32];

/* ---------------- bf16 helpers (bit-level, rn-even) ----------------------- */
__device__ __forceinline__ unsigned short f2bf(float x) {
    unsigned u = __float_as_uint(x);
    u = u + 0x7fffu + ((u >> 16) & 1u);
    return (unsigned short)(u >> 16);
}
__device__ __forceinline__ float bf2f(unsigned short s) {
    return __uint_as_float(((unsigned)s) << 16);
}

__device__ __forceinline__ unsigned s2u(const void* p) {
    unsigned a;
    asm("{ .reg .u64 t; cvta.to.shared.u64 t, %1; cvt.u32.u64 %0, t; }"
        : "=r"(a) : "l"(p));
    return a;
}

/* ---------------- packed f32x2 FMA (attention) ---------------------------- */
union F2U { float2 f; unsigned long long u; };
__device__ __forceinline__ float2 ffma2(float2 a, float2 b, float2 c) {
    F2U A, Bu, C, D;
    A.f = a; Bu.f = b; C.f = c;
    asm("fma.rn.f32x2 %0, %1, %2, %3;" : "=l"(D.u) : "l"(A.u), "l"(Bu.u), "l"(C.u));
    return D.f;
}

/* ---------------- mma.sync / ldmatrix / cp.async (baseline PTX) ----------- */
__device__ __forceinline__ void ldmx4(unsigned* r, unsigned a) {
    asm volatile("ldmatrix.sync.aligned.m8n8.x4.shared.b16 {%0,%1,%2,%3}, [%4];"
                 : "=r"(r[0]), "=r"(r[1]), "=r"(r[2]), "=r"(r[3]) : "r"(a));
}
__device__ __forceinline__ void mma_bf16(float* c, const unsigned* a,
                                         unsigned b0, unsigned b1) {
    asm volatile("mma.sync.aligned.m16n8k16.row.col.f32.bf16.bf16.f32 "
                 "{%0,%1,%2,%3}, {%4,%5,%6,%7}, {%8,%9}, {%0,%1,%2,%3};"
                 : "+f"(c[0]), "+f"(c[1]), "+f"(c[2]), "+f"(c[3])
                 : "r"(a[0]), "r"(a[1]), "r"(a[2]), "r"(a[3]), "r"(b0), "r"(b1));
}
__device__ __forceinline__ void cpa16(unsigned dst, const void* src) {
    asm volatile("cp.async.cg.shared.global [%0], [%1], 16;"
                 :: "r"(dst), "l"(src));
}
__device__ __forceinline__ void cp_commit() {
    asm volatile("cp.async.commit_group;" ::: "memory");
}
__device__ __forceinline__ void cp_wait2() {
    asm volatile("cp.async.wait_group 2;" ::: "memory");
}

/* ---------------- RoPE table (fp64 for large-angle accuracy) -------------- */
__global__ void rope_table_kernel(const int* __restrict__ pos_offset) {
    int idx = blockIdx.x * blockDim.x + threadIdx.x;
    if (idx >= SEQT * 32) return;
    int t = idx >> 5, p = idx & 31;
    double inv = exp(-((double)(2 * p) / 64.0) * log(10000.0));
    double ang = (double)(*pos_offset + t) * inv;
    g_cos[idx] = (float)cos(ang);
    g_sin[idx] = (float)sin(ang);
}

/* ---------------- bf16 hi/lo split of X and the 4 weight matrices --------- */
__global__ void convert_kernel(const float* __restrict__ X,
                               const float* __restrict__ Wq,
                               const float* __restrict__ Wk,
                               const float* __restrict__ Wv,
                               const float* __restrict__ Wo) {
    size_t i4 = (size_t)blockIdx.x * blockDim.x + threadIdx.x;
    size_t e = i4 * 4;
    const float* src;
    unsigned short *dhi, *dlo;
    size_t off;
    if (e < (size_t)XN) {
        src = X; dhi = g_xhi; dlo = g_xlo; off = e;
    } else {
        size_t r = e - XN;
        int w = (int)(r / WN);
        off = r % WN;
        src = (w == 0) ? Wq : (w == 1) ? Wk : (w == 2) ? Wv : Wo;
        dhi = g_whi + (size_t)w * WN;
        dlo = g_wlo + (size_t)w * WN;
    }
    float4 v = *(const float4*)(src + off);
    unsigned short h0 = f2bf(v.x), h1 = f2bf(v.y), h2 = f2bf(v.z), h3 = f2bf(v.w);
    unsigned short l0 = f2bf(v.x - bf2f(h0)), l1 = f2bf(v.y - bf2f(h1));
    unsigned short l2 = f2bf(v.z - bf2f(h2)), l3 = f2bf(v.w - bf2f(h3));
    *(uint2*)(dhi + off) = make_uint2((unsigned)h0 | ((unsigned)h1 << 16),
                                      (unsigned)h2 | ((unsigned)h3 << 16));
    *(uint2*)(dlo + off) = make_uint2((unsigned)l0 | ((unsigned)l1 << 16),
                                      (unsigned)l2 | ((unsigned)l3 << 16));
}

/* ---------------- cache copy: new_{k,v}[:, :, 0:256] = past[:, :, 256:512] */
__global__ void copy_cache_kernel(const float4* __restrict__ pk,
                                  const float4* __restrict__ pv,
                                  float4* __restrict__ nk,
                                  float4* __restrict__ nv) {
    int idx = blockIdx.x * blockDim.x + threadIdx.x;
    int which = idx >> 21;
    int r     = idx & ((1 << 21) - 1);
    int bh    = r >> 12;
    int e     = r & 4095;
    const float4* src = which ? pv : pk;
    float4*       dst = which ? nv : nk;
    dst[(size_t)bh * 8192 + e] = src[(size_t)bh * 8192 + 4096 + e];
}

/* ================= bf16-split mma.sync GEMM  C = A @ W^T ==================
   CTA 128x256, BK=32 bf16, 16 warps (4x4) each 32x64, 3-stage cp.async.
   R10 post-mortem: tensor stuck ~52% with 2 warps/SMSP (latency-bound, not
   smem-bound). 512 threads -> 4 warps/SMSP for latency hiding; warp tile
   32x64 keeps accumulators at 64 f32/thread so 512 threads fit the RF.
   B fragments are prefetched one np-group ahead.                           */
#define KC 32
#define NCHUNK (MDIM / KC)             /* 64 */
#define BN_CTA 256
#define GTHREADS 512
#define SSTRIDE 80                     /* bytes per smem row */
#define A_BYTES (128 * SSTRIDE)        /* 10240 */
#define B_BYTES (BN_CTA * SSTRIDE)     /* 20480 */
#define STAGE_BYTES (2 * A_BYTES + 2 * B_BYTES)  /* 61440 */
#define NSTAGE 3
#define GSMEM (NSTAGE * STAGE_BYTES)   /* 184320 */

__device__ __forceinline__ void stage_load(unsigned sbase, int stage,
        const unsigned short* __restrict__ Ahi, const unsigned short* __restrict__ Alo,
        const unsigned short* __restrict__ Bhi, const unsigned short* __restrict__ Blo,
        int m0, int n0, int kb, int tid) {
    unsigned st = sbase + stage * STAGE_BYTES;
    {                                             /* A: 128 rows x 32 cols */
        int row = tid >> 2, c8 = (tid & 3) * 8;   /* tid 0..511 exactly    */
        size_t ga = (size_t)(m0 + row) * MDIM + kb + c8;
        unsigned d = st + row * SSTRIDE + c8 * 2;
        cpa16(d,           Ahi + ga);
        cpa16(d + A_BYTES, Alo + ga);
    }
#pragma unroll
    for (int i = 0; i < 2; i++) {                 /* B: 256 rows x 32 cols */
        int op = tid + i * GTHREADS;              /* 0..1023 */
        int row = op >> 2, c8 = (op & 3) * 8;
        size_t gb = (size_t)(n0 + row) * MDIM + kb + c8;
        unsigned d = st + 2 * A_BYTES + row * SSTRIDE + c8 * 2;
        cpa16(d,           Bhi + gb);
        cpa16(d + B_BYTES, Blo + gb);
    }
}

/* MODE 0: Q (rope -> g_q)      MODE 1: K (raw -> nk, rope -> g_krot)
   MODE 2: V (raw -> nv)        MODE 3: O (plain -> out)                    */
template <int MODE>
__device__ __forceinline__ void gemm_tc(
        const unsigned short* __restrict__ Ahi, const unsigned short* __restrict__ Alo,
        const unsigned short* __restrict__ Bhi, const unsigned short* __restrict__ Blo,
        float* __restrict__ dst) {
    extern __shared__ char sm[];
    unsigned sbase = s2u(sm);
    int tid = threadIdx.x, wid = tid >> 5, lane = tid & 31;
    int m0 = blockIdx.y * 128, n0 = blockIdx.x * BN_CTA;
    int warp_m = (wid >> 2) * 32, warp_n = (wid & 3) * 64;

    float c[2][8][4];
#pragma unroll
    for (int mt = 0; mt < 2; mt++)
#pragma unroll
        for (int nt = 0; nt < 8; nt++)
#pragma unroll
            for (int q = 0; q < 4; q++) c[mt][nt][q] = 0.f;

    stage_load(sbase, 0, Ahi, Alo, Bhi, Blo, m0, n0, 0,  tid); cp_commit();
    stage_load(sbase, 1, Ahi, Alo, Bhi, Blo, m0, n0, KC, tid); cp_commit();

    /* lane-dependent parts of ldmatrix addresses */
    unsigned aoff = (warp_m + (lane & 15)) * SSTRIDE + ((lane >> 4) << 4);
    unsigned boff = (warp_n + ((lane >> 4) << 3) + (lane & 7)) * SSTRIDE
                  + (((lane >> 3) & 1) << 4) + 2 * A_BYTES;

    for (int ch = 0; ch < NCHUNK; ch++) {
        if (ch + 2 < NCHUNK)
            stage_load(sbase, (ch + 2) % NSTAGE, Ahi, Alo, Bhi, Blo,
                       m0, n0, (ch + 2) * KC, tid);
        cp_commit();
        cp_wait2();
        __syncthreads();

        unsigned st = sbase + (ch % NSTAGE) * STAGE_BYTES;
#pragma unroll
        for (int ks = 0; ks < 2; ks++) {
            unsigned ah[2][4], al[2][4];
#pragma unroll
            for (int mt = 0; mt < 2; mt++) {
                unsigned a = st + aoff + mt * (16 * SSTRIDE) + ks * 32;
                ldmx4(ah[mt], a);
                ldmx4(al[mt], a + A_BYTES);
            }
            /* B double-buffer: prefetch np+1 while mma-ing np */
            unsigned bh[2][4], bl[2][4];
            {
                unsigned a = st + boff + ks * 32;
                ldmx4(bh[0], a);
                ldmx4(bl[0], a + B_BYTES);
            }
#pragma unroll
            for (int np = 0; np < 4; np++) {
                int cur = np & 1, nxt = cur ^ 1;
                if (np < 3) {
                    unsigned a = st + boff + (np + 1) * (16 * SSTRIDE) + ks * 32;
                    ldmx4(bh[nxt], a);
                    ldmx4(bl[nxt], a + B_BYTES);
                }
                int n0t = 2 * np, n1t = 2 * np + 1;
#pragma unroll
                for (int mt = 0; mt < 2; mt++) {
                    mma_bf16(c[mt][n0t], ah[mt], bh[cur][0], bh[cur][1]);
                    mma_bf16(c[mt][n1t], ah[mt], bh[cur][2], bh[cur][3]);
                }
#pragma unroll
                for (int mt = 0; mt < 2; mt++) {
                    mma_bf16(c[mt][n0t], ah[mt], bl[cur][0], bl[cur][1]);
                    mma_bf16(c[mt][n1t], ah[mt], bl[cur][2], bl[cur][3]);
                }
#pragma unroll
                for (int mt = 0; mt < 2; mt++) {
                    mma_bf16(c[mt][n0t], al[mt], bh[cur][0], bh[cur][1]);
                    mma_bf16(c[mt][n1t], al[mt], bh[cur][2], bh[cur][3]);
                }
            }
        }
        __syncthreads();
    }

    /* epilogue: frag (mt,nt): rows m0+warp_m+mt*16+(lane>>2)(+8),
       cols n0+warp_n+nt*8+(lane&3)*2                                      */
    int mb = m0 + warp_m + (lane >> 2);
    int nb = n0 + warp_n + (lane & 3) * 2;
#pragma unroll
    for (int mt = 0; mt < 2; mt++) {
#pragma unroll
        for (int half = 0; half < 2; half++) {
            int m = mb + mt * 16 + half * 8;
#pragma unroll
            for (int nt = 0; nt < 8; nt++) {
                int n = nb + nt * 8;
                float x = c[mt][nt][half * 2], y = c[mt][nt][half * 2 + 1];
                if (MODE == 3) {
                    *(float2*)(dst + (size_t)m * MDIM + n) = make_float2(x, y);
                } else {
                    int b = m >> 8, t = m & 255;
                    int h = n >> 6, hd = n & 63;
                    int bh_ = b * NHEAD + h;
                    if (MODE == 2) {
                        *(float2*)(dst + ((size_t)bh_ * SWIN + SEQT + t) * HDIM + hd)
                            = make_float2(x, y);
                    } else {
                        int p = hd >> 1;
                        float cth = g_cos[t * 32 + p], sth = g_sin[t * 32 + p];
                        float rx = x * cth - y * sth;
                        float ry = x * sth + y * cth;
                        if (MODE == 0) {
                            *(float2*)(g_q + ((size_t)bh_ * SEQT + t) * HDIM + hd)
                                = make_float2(rx, ry);
                        } else {
                            *(float2*)(dst + ((size_t)bh_ * SWIN + SEQT + t) * HDIM + hd)
                                = make_float2(x, y);
                            *(float2*)(g_krot + ((size_t)bh_ * SEQT + t) * HDIM + hd)
                                = make_float2(rx, ry);
                        }
                    }
                }
            }
        }
    }
}

__global__ void __launch_bounds__(GTHREADS, 1)
gemm_qkv_tc(float* __restrict__ nk, float* __restrict__ nv) {
    if      (blockIdx.z == 0) gemm_tc<0>(g_xhi, g_xlo, g_whi,          g_wlo,          nullptr);
    else if (blockIdx.z == 1) gemm_tc<1>(g_xhi, g_xlo, g_whi + 1u*WN,  g_wlo + 1u*WN,  nk);
    else                      gemm_tc<2>(g_xhi, g_xlo, g_whi + 2u*WN,  g_wlo + 2u*WN,  nv);
}

__global__ void __launch_bounds__(GTHREADS, 1)
gemm_o_tc(float* __restrict__ out) {
    gemm_tc<3>(g_ahi, g_alo, g_whi + 3u*WN, g_wlo + 3u*WN, out);
}

/* ---------------- flash-style attention: 64q x 64k tiles ------------------ */
#define APAD 68
#define ATT_SMEM (4 * 64 * APAD * (int)sizeof(float))   /* 69632 B */

__global__ void __launch_bounds__(256)
attn_kernel(const float* __restrict__ nk, const float* __restrict__ nv) {
    extern __shared__ float smd[];
    float* Qs = smd;
    float* Ks = Qs + 64 * APAD;
    float* Vs = Ks + 64 * APAD;
    float* Ps = Vs + 64 * APAD;

    int qt  = blockIdx.x;
    int bh  = blockIdx.y;
    int tid = threadIdx.x;
    int tx = tid & 15, ty = tid >> 4;

    const float* qbase = g_q + ((size_t)bh * SEQT + qt * 64) * HDIM;
    for (int f = tid; f < 1024; f += 256) {
        int r = f >> 4, c4 = (f & 15) << 2;
        float4 v = *(const float4*)(qbase + r * 64 + c4);
        Qs[(c4 + 0) * APAD + r] = v.x * 0.125f;
        Qs[(c4 + 1) * APAD + r] = v.y * 0.125f;
        Qs[(c4 + 2) * APAD + r] = v.z * 0.125f;
        Qs[(c4 + 3) * APAD + r] = v.w * 0.125f;
    }

    float2 acc[4][2];
    float  mrow[4], lrow[4];
#pragma unroll
    for (int r = 0; r < 4; r++) {
        acc[r][0] = acc[r][1] = make_float2(0.f, 0.f);
        mrow[r] = -INFINITY; lrow[r] = 0.f;
    }

    int ktmax = qt + 4;
    for (int kt = 0; kt <= ktmax; kt++) {
        const float* kb = (kt < 4)
            ? (nk     + ((size_t)bh * SWIN + kt * 64) * HDIM)
            : (g_krot + ((size_t)bh * SEQT + (kt - 4) * 64) * HDIM);
        const float* vb = nv + ((size_t)bh * SWIN + kt * 64) * HDIM;

        __syncthreads();
        for (int f = tid; f < 1024; f += 256) {
            int r = f >> 4, c4 = (f & 15) << 2;
            float4 v = *(const float4*)(kb + r * 64 + c4);
            Ks[(c4 + 0) * APAD + r] = v.x;
            Ks[(c4 + 1) * APAD + r] = v.y;
            Ks[(c4 + 2) * APAD + r] = v.z;
            Ks[(c4 + 3) * APAD + r] = v.w;
            float4 w = *(const float4*)(vb + r * 64 + c4);
            *(float4*)&Vs[r * APAD + c4] = w;
        }
        __syncthreads();

        float2 s2[4][2];
#pragma unroll
        for (int r = 0; r < 4; r++) s2[r][0] = s2[r][1] = make_float2(0.f, 0.f);
#pragma unroll 8
        for (int d = 0; d < 64; d++) {
            float4 a  = *(const float4*)&Qs[d * APAD + ty * 4];
            float4 bq = *(const float4*)&Ks[d * APAD + tx * 4];
            float2 b01 = make_float2(bq.x, bq.y), b23 = make_float2(bq.z, bq.w);
            float  av[4] = {a.x, a.y, a.z, a.w};
#pragma unroll
            for (int r = 0; r < 4; r++) {
                float2 ad = make_float2(av[r], av[r]);
                s2[r][0] = ffma2(ad, b01, s2[r][0]);
                s2[r][1] = ffma2(ad, b23, s2[r][1]);
            }
        }
        float s[4][4];
#pragma unroll
        for (int r = 0; r < 4; r++) {
            s[r][0] = s2[r][0].x; s[r][1] = s2[r][0].y;
            s[r][2] = s2[r][1].x; s[r][3] = s2[r][1].y;
        }
        if (kt == qt + 4) {
#pragma unroll
            for (int r = 0; r < 4; r++)
#pragma unroll
                for (int cc = 0; cc < 4; cc++)
                    if (tx * 4 + cc > ty * 4 + r) s[r][cc] = -INFINITY;
        }
#pragma unroll
        for (int r = 0; r < 4; r++) {
            float rm = fmaxf(fmaxf(s[r][0], s[r][1]), fmaxf(s[r][2], s[r][3]));
#pragma unroll
            for (int o = 8; o >= 1; o >>= 1)
                rm = fmaxf(rm, __shfl_xor_sync(0xffffffffu, rm, o));
            float mnew = fmaxf(mrow[r], rm);
            float fct  = __expf(mrow[r] - mnew);
            mrow[r] = mnew;
            float p[4], psum = 0.f;
#pragma unroll
            for (int cc = 0; cc < 4; cc++) { p[cc] = __expf(s[r][cc] - mnew); psum += p[cc]; }
#pragma unroll
            for (int o = 8; o >= 1; o >>= 1)
                psum += __shfl_xor_sync(0xffffffffu, psum, o);
            lrow[r] = lrow[r] * fct + psum;
            acc[r][0].x *= fct; acc[r][0].y *= fct;
            acc[r][1].x *= fct; acc[r][1].y *= fct;
            *(float4*)&Ps[(ty * 4 + r) * APAD + tx * 4] = make_float4(p[0], p[1], p[2], p[3]);
        }
        __syncthreads();
#pragma unroll 4
        for (int j = 0; j < 64; j++) {
            float4 vv = *(const float4*)&Vs[j * APAD + tx * 4];
            float2 v01 = make_float2(vv.x, vv.y), v23 = make_float2(vv.z, vv.w);
#pragma unroll
            for (int r = 0; r < 4; r++) {
                float  pr = Ps[(ty * 4 + r) * APAD + j];
                float2 pd = make_float2(pr, pr);
                acc[r][0] = ffma2(pd, v01, acc[r][0]);
                acc[r][1] = ffma2(pd, v23, acc[r][1]);
            }
        }
    }

    /* epilogue -> bf16 hi/lo split, consumed by the O GEMM */
    int b = bh >> 5, h = bh & 31;
#pragma unroll
    for (int r = 0; r < 4; r++) {
        int   t   = qt * 64 + ty * 4 + r;
        float inv = 1.f / lrow[r];
        float o0 = acc[r][0].x * inv, o1 = acc[r][0].y * inv;
        float o2 = acc[r][1].x * inv, o3 = acc[r][1].y * inv;
        unsigned short h0 = f2bf(o0), h1 = f2bf(o1), h2 = f2bf(o2), h3 = f2bf(o3);
        unsigned short l0 = f2bf(o0 - bf2f(h0)), l1 = f2bf(o1 - bf2f(h1));
        unsigned short l2 = f2bf(o2 - bf2f(h2)), l3 = f2bf(o3 - bf2f(h3));
        size_t idx = ((size_t)(b * SEQT + t)) * MDIM + h * HDIM + tx * 4;
        *(uint2*)(g_ahi + idx) = make_uint2((unsigned)h0 | ((unsigned)h1 << 16),
                                            (unsigned)h2 | ((unsigned)h3 << 16));
        *(uint2*)(g_alo + idx) = make_uint2((unsigned)l0 | ((unsigned)l1 << 16),
                                            (unsigned)l2 | ((unsigned)l3 << 16));
    }
}

/* ---------------- launch -------------------------------------------------- */
extern "C" void kernel_launch(void* const* d_in, const int* in_sizes, int n_in,
                              void* d_out, int out_size) {
    (void)in_sizes; (void)n_in; (void)out_size;
    const float* x  = (const float*)d_in[0];
    const float* pk = (const float*)d_in[1];
    const float* pv = (const float*)d_in[2];
    const float* Wq = (const float*)d_in[3];
    const float* Wk = (const float*)d_in[4];
    const float* Wv = (const float*)d_in[5];
    const float* Wo = (const float*)d_in[6];
    const int*  pos = (const int*)d_in[7];

    float* out = (float*)d_out;
    float* nk  = out + (size_t)MROWS * MDIM;
    float* nv  = nk + (size_t)BATCH * NHEAD * SWIN * HDIM;

    cudaFuncSetAttribute(attn_kernel,
                         cudaFuncAttributeMaxDynamicSharedMemorySize, ATT_SMEM);
    cudaFuncSetAttribute(gemm_qkv_tc,
                         cudaFuncAttributeMaxDynamicSharedMemorySize, GSMEM);
    cudaFuncSetAttribute(gemm_o_tc,
                         cudaFuncAttributeMaxDynamicSharedMemorySize, GSMEM);

    rope_table_kernel<<<32, 256>>>(pos);
    convert_kernel<<<(XN + 4 * WN) / 4 / 256, 256>>>(x, Wq, Wk, Wv, Wo);
    copy_cache_kernel<<<(2 * (1 << 21)) / 256, 256>>>(
        (const float4*)pk, (const float4*)pv, (float4*)nk, (float4*)nv);
    gemm_qkv_tc<<<dim3(MDIM / BN_CTA, MROWS / 128, 3), GTHREADS, GSMEM>>>(nk, nv);
    attn_kernel<<<dim3(4, BATCH * NHEAD), 256, ATT_SMEM>>>(nk, nv);
    gemm_o_tc<<<dim3(MDIM / BN_CTA, MROWS / 128, 1), GTHREADS, GSMEM>>>(out);
}

// round 12
// speedup vs baseline: 1.1181x; 1.1181x over previous
#include <cuda_runtime.h>
#include <math.h>

#define MDIM  2048
#define NHEAD 32
#define HDIM  64
#define BATCH 16
#define SEQT  256
#define SWIN  512
#define MROWS (BATCH*SEQT)          /* 4096 */
#define WN    (MDIM*MDIM)           /* 4194304 */
#define XN    (MROWS*MDIM)          /* 8388608 */
#define KVN   (BATCH*NHEAD*SWIN*HDIM)   /* 16777216 */
#define QN    (BATCH*NHEAD*SEQT*HDIM)   /*  8388608 */

/* ---------------- scratch (static device arrays; no cudaMalloc) ---------- */
__device__ unsigned short g_xhi[XN], g_xlo[XN];            /* X  bf16 split */
__device__ unsigned short g_whi[4u*WN], g_wlo[4u*WN];      /* Wq,Wk,Wv,Wo   */
__device__ unsigned short g_ahi[XN], g_alo[XN];            /* attn out split */
__device__ unsigned short g_qhi[QN], g_qlo[QN];            /* rope'd Q/8     */
__device__ unsigned short g_khi[KVN], g_klo[KVN];          /* K window bf16  */
__device__ unsigned short g_vhi[KVN], g_vlo[KVN];          /* V window bf16  */
__device__ float          g_cos[SEQT*32], g_sin[SEQT*32];

/* ---------------- bf16 helpers (bit-level, rn-even) ----------------------- */
__device__ __forceinline__ unsigned short f2bf(float x) {
    unsigned u = __float_as_uint(x);
    u = u + 0x7fffu + ((u >> 16) & 1u);
    return (unsigned short)(u >> 16);
}
__device__ __forceinline__ float bf2f(unsigned short s) {
    return __uint_as_float(((unsigned)s) << 16);
}
__device__ __forceinline__ unsigned pack2(float x, float y) {
    return (unsigned)f2bf(x) | ((unsigned)f2bf(y) << 16);
}
__device__ __forceinline__ unsigned pack2lo(float x, float y,
                                            unsigned hi) {
    float lx = x - __uint_as_float((hi & 0xffffu) << 16);
    float ly = y - __uint_as_float((hi & 0xffff0000u));
    return (unsigned)f2bf(lx) | ((unsigned)f2bf(ly) << 16);
}

__device__ __forceinline__ unsigned s2u(const void* p) {
    unsigned a;
    asm("{ .reg .u64 t; cvta.to.shared.u64 t, %1; cvt.u32.u64 %0, t; }"
        : "=r"(a) : "l"(p));
    return a;
}

/* ---------------- mma.sync / ldmatrix / cp.async (baseline PTX) ----------- */
__device__ __forceinline__ void ldmx4(unsigned* r, unsigned a) {
    asm volatile("ldmatrix.sync.aligned.m8n8.x4.shared.b16 {%0,%1,%2,%3}, [%4];"
                 : "=r"(r[0]), "=r"(r[1]), "=r"(r[2]), "=r"(r[3]) : "r"(a));
}
__device__ __forceinline__ void ldmx4t(unsigned* r, unsigned a) {
    asm volatile("ldmatrix.sync.aligned.m8n8.x4.trans.shared.b16 {%0,%1,%2,%3}, [%4];"
                 : "=r"(r[0]), "=r"(r[1]), "=r"(r[2]), "=r"(r[3]) : "r"(a));
}
__device__ __forceinline__ void mma_bf16(float* c, const unsigned* a,
                                         unsigned b0, unsigned b1) {
    asm volatile("mma.sync.aligned.m16n8k16.row.col.f32.bf16.bf16.f32 "
                 "{%0,%1,%2,%3}, {%4,%5,%6,%7}, {%8,%9}, {%0,%1,%2,%3};"
                 : "+f"(c[0]), "+f"(c[1]), "+f"(c[2]), "+f"(c[3])
                 : "r"(a[0]), "r"(a[1]), "r"(a[2]), "r"(a[3]), "r"(b0), "r"(b1));
}
__device__ __forceinline__ void cpa16(unsigned dst, const void* src) {
    asm volatile("cp.async.cg.shared.global [%0], [%1], 16;"
                 :: "r"(dst), "l"(src));
}
__device__ __forceinline__ void cp_commit() {
    asm volatile("cp.async.commit_group;" ::: "memory");
}
__device__ __forceinline__ void cp_wait2() {
    asm volatile("cp.async.wait_group 2;" ::: "memory");
}
__device__ __forceinline__ void cp_wait1() {
    asm volatile("cp.async.wait_group 1;" ::: "memory");
}

/* ---------------- RoPE table (fp64 for large-angle accuracy) -------------- */
__global__ void rope_table_kernel(const int* __restrict__ pos_offset) {
    int idx = blockIdx.x * blockDim.x + threadIdx.x;
    if (idx >= SEQT * 32) return;
    int t = idx >> 5, p = idx & 31;
    double inv = exp(-((double)(2 * p) / 64.0) * log(10000.0));
    double ang = (double)(*pos_offset + t) * inv;
    g_cos[idx] = (float)cos(ang);
    g_sin[idx] = (float)sin(ang);
}

/* ---------------- bf16 hi/lo split of X and the 4 weight matrices --------- */
__global__ void convert_kernel(const float* __restrict__ X,
                               const float* __restrict__ Wq,
                               const float* __restrict__ Wk,
                               const float* __restrict__ Wv,
                               const float* __restrict__ Wo) {
    size_t i4 = (size_t)blockIdx.x * blockDim.x + threadIdx.x;
    size_t e = i4 * 4;
    const float* src;
    unsigned short *dhi, *dlo;
    size_t off;
    if (e < (size_t)XN) {
        src = X; dhi = g_xhi; dlo = g_xlo; off = e;
    } else {
        size_t r = e - XN;
        int w = (int)(r / WN);
        off = r % WN;
        src = (w == 0) ? Wq : (w == 1) ? Wk : (w == 2) ? Wv : Wo;
        dhi = g_whi + (size_t)w * WN;
        dlo = g_wlo + (size_t)w * WN;
    }
    float4 v = *(const float4*)(src + off);
    unsigned h01 = pack2(v.x, v.y), h23 = pack2(v.z, v.w);
    unsigned l01 = pack2lo(v.x, v.y, h01), l23 = pack2lo(v.z, v.w, h23);
    *(uint2*)(dhi + off) = make_uint2(h01, h23);
    *(uint2*)(dlo + off) = make_uint2(l01, l23);
}

/* -------- cache copy + bf16 split of past window ------------------------- */
__global__ void copy_cache_kernel(const float4* __restrict__ pk,
                                  const float4* __restrict__ pv,
                                  float4* __restrict__ nk,
                                  float4* __restrict__ nv) {
    int idx = blockIdx.x * blockDim.x + threadIdx.x;
    int which = idx >> 21;
    int r     = idx & ((1 << 21) - 1);
    int bh    = r >> 12;
    int e     = r & 4095;
    const float4* src = which ? pv : pk;
    float4*       dst = which ? nv : nk;
    float4 v = src[(size_t)bh * 8192 + 4096 + e];
    dst[(size_t)bh * 8192 + e] = v;
    /* bf16 split into rows 0..255 of the attention K/V window */
    int row = e >> 4, dcol = (e & 15) * 4;
    size_t si = ((size_t)bh * SWIN + row) * HDIM + dcol;
    unsigned short* dh = which ? g_vhi : g_khi;
    unsigned short* dl = which ? g_vlo : g_klo;
    unsigned h01 = pack2(v.x, v.y), h23 = pack2(v.z, v.w);
    *(uint2*)(dh + si) = make_uint2(h01, h23);
    *(uint2*)(dl + si) = make_uint2(pack2lo(v.x, v.y, h01), pack2lo(v.z, v.w, h23));
}

/* ================= bf16-split mma.sync GEMM  C = A @ W^T (R9 config) =====
   CTA 128x128, BK=32 bf16, 8 warps (2x4) each 64x32, 3-stage cp.async.    */
#define KC 32
#define NCHUNK (MDIM / KC)             /* 64 */
#define SSTRIDE 80                     /* bytes per smem row */
#define COMP_BYTES (128 * SSTRIDE)     /* 10240 */
#define STAGE_BYTES (4 * COMP_BYTES)   /* 40960 */
#define NSTAGE 3
#define GSMEM (NSTAGE * STAGE_BYTES)   /* 122880 */

__device__ __forceinline__ void stage_load(unsigned sbase, int stage,
        const unsigned short* __restrict__ Ahi, const unsigned short* __restrict__ Alo,
        const unsigned short* __restrict__ Bhi, const unsigned short* __restrict__ Blo,
        int m0, int n0, int kb, int tid) {
    unsigned st = sbase + stage * STAGE_BYTES;
#pragma unroll
    for (int i = 0; i < 2; i++) {
        int op = tid + i * 256;
        int row = op >> 2, c8 = (op & 3) * 8;
        size_t ga = (size_t)(m0 + row) * MDIM + kb + c8;
        size_t gb = (size_t)(n0 + row) * MDIM + kb + c8;
        unsigned d = st + row * SSTRIDE + c8 * 2;
        cpa16(d,                  Ahi + ga);
        cpa16(d + COMP_BYTES,     Alo + ga);
        cpa16(d + 2 * COMP_BYTES, Bhi + gb);
        cpa16(d + 3 * COMP_BYTES, Blo + gb);
    }
}

/* MODE 0: Q (rope, /8, split -> g_qhi/qlo)
   MODE 1: K (fp32 -> nk; rope split -> g_khi/klo rows 256..)
   MODE 2: V (fp32 -> nv; split -> g_vhi/vlo rows 256..)
   MODE 3: O (plain fp32 -> out)                                            */
template <int MODE>
__device__ __forceinline__ void gemm_tc(
        const unsigned short* __restrict__ Ahi, const unsigned short* __restrict__ Alo,
        const unsigned short* __restrict__ Bhi, const unsigned short* __restrict__ Blo,
        float* __restrict__ dst) {
    extern __shared__ char sm[];
    unsigned sbase = s2u(sm);
    int tid = threadIdx.x, wid = tid >> 5, lane = tid & 31;
    int m0 = blockIdx.y * 128, n0 = blockIdx.x * 128;
    int warp_m = (wid >> 2) * 64, warp_n = (wid & 3) * 32;

    float c[4][4][4];
#pragma unroll
    for (int mt = 0; mt < 4; mt++)
#pragma unroll
        for (int nt = 0; nt < 4; nt++)
#pragma unroll
            for (int q = 0; q < 4; q++) c[mt][nt][q] = 0.f;

    stage_load(sbase, 0, Ahi, Alo, Bhi, Blo, m0, n0, 0,  tid); cp_commit();
    stage_load(sbase, 1, Ahi, Alo, Bhi, Blo, m0, n0, KC, tid); cp_commit();

    unsigned aoff = (warp_m + (lane & 15)) * SSTRIDE + ((lane >> 4) << 4);
    unsigned boff = (warp_n + ((lane >> 4) << 3) + (lane & 7)) * SSTRIDE
                  + (((lane >> 3) & 1) << 4) + 2 * COMP_BYTES;

    for (int ch = 0; ch < NCHUNK; ch++) {
        if (ch + 2 < NCHUNK)
            stage_load(sbase, (ch + 2) % NSTAGE, Ahi, Alo, Bhi, Blo,
                       m0, n0, (ch + 2) * KC, tid);
        cp_commit();
        cp_wait2();
        __syncthreads();

        unsigned st = sbase + (ch % NSTAGE) * STAGE_BYTES;
#pragma unroll
        for (int ks = 0; ks < 2; ks++) {
            unsigned ah[4][4], al[4][4], bh[2][4], bl[2][4];
#pragma unroll
            for (int mt = 0; mt < 4; mt++) {
                unsigned a = st + aoff + mt * (16 * SSTRIDE) + ks * 32;
                ldmx4(ah[mt], a);
                ldmx4(al[mt], a + COMP_BYTES);
            }
#pragma unroll
            for (int np = 0; np < 2; np++) {
                unsigned a = st + boff + np * (16 * SSTRIDE) + ks * 32;
                ldmx4(bh[np], a);
                ldmx4(bl[np], a + COMP_BYTES);
            }
#pragma unroll
            for (int mt = 0; mt < 4; mt++)
#pragma unroll
                for (int nt = 0; nt < 4; nt++)
                    mma_bf16(c[mt][nt], ah[mt],
                             bh[nt >> 1][(nt & 1) * 2], bh[nt >> 1][(nt & 1) * 2 + 1]);
#pragma unroll
            for (int mt = 0; mt < 4; mt++)
#pragma unroll
                for (int nt = 0; nt < 4; nt++)
                    mma_bf16(c[mt][nt], ah[mt],
                             bl[nt >> 1][(nt & 1) * 2], bl[nt >> 1][(nt & 1) * 2 + 1]);
#pragma unroll
            for (int mt = 0; mt < 4; mt++)
#pragma unroll
                for (int nt = 0; nt < 4; nt++)
                    mma_bf16(c[mt][nt], al[mt],
                             bh[nt >> 1][(nt & 1) * 2], bh[nt >> 1][(nt & 1) * 2 + 1]);
        }
        __syncthreads();
    }

    int mb = m0 + warp_m + (lane >> 2);
    int nb = n0 + warp_n + (lane & 3) * 2;
#pragma unroll
    for (int mt = 0; mt < 4; mt++) {
#pragma unroll
        for (int half = 0; half < 2; half++) {
            int m = mb + mt * 16 + half * 8;
#pragma unroll
            for (int nt = 0; nt < 4; nt++) {
                int n = nb + nt * 8;
                float x = c[mt][nt][half * 2], y = c[mt][nt][half * 2 + 1];
                if (MODE == 3) {
                    *(float2*)(dst + (size_t)m * MDIM + n) = make_float2(x, y);
                } else {
                    int b = m >> 8, t = m & 255;
                    int h = n >> 6, hd = n & 63;
                    int bh_ = b * NHEAD + h;
                    if (MODE == 2) {
                        *(float2*)(dst + ((size_t)bh_ * SWIN + SEQT + t) * HDIM + hd)
                            = make_float2(x, y);
                        size_t si = ((size_t)bh_ * SWIN + SEQT + t) * HDIM + hd;
                        unsigned hp = pack2(x, y);
                        *(unsigned*)(g_vhi + si) = hp;
                        *(unsigned*)(g_vlo + si) = pack2lo(x, y, hp);
                    } else {
                        int p = hd >> 1;
                        float cth = g_cos[t * 32 + p], sth = g_sin[t * 32 + p];
                        float rx = x * cth - y * sth;
                        float ry = x * sth + y * cth;
                        if (MODE == 0) {
                            size_t si = ((size_t)bh_ * SEQT + t) * HDIM + hd;
                            float qx = rx * 0.125f, qy = ry * 0.125f;
                            unsigned hp = pack2(qx, qy);
                            *(unsigned*)(g_qhi + si) = hp;
                            *(unsigned*)(g_qlo + si) = pack2lo(qx, qy, hp);
                        } else {
                            *(float2*)(dst + ((size_t)bh_ * SWIN + SEQT + t) * HDIM + hd)
                                = make_float2(x, y);
                            size_t si = ((size_t)bh_ * SWIN + SEQT + t) * HDIM + hd;
                            unsigned hp = pack2(rx, ry);
                            *(unsigned*)(g_khi + si) = hp;
                            *(unsigned*)(g_klo + si) = pack2lo(rx, ry, hp);
                        }
                    }
                }
            }
        }
    }
}

__global__ void __launch_bounds__(256, 1)
gemm_qkv_tc(float* __restrict__ nk, float* __restrict__ nv) {
    if      (blockIdx.z == 0) gemm_tc<0>(g_xhi, g_xlo, g_whi,          g_wlo,          nullptr);
    else if (blockIdx.z == 1) gemm_tc<1>(g_xhi, g_xlo, g_whi + 1u*WN,  g_wlo + 1u*WN,  nk);
    else                      gemm_tc<2>(g_xhi, g_xlo, g_whi + 2u*WN,  g_wlo + 2u*WN,  nv);
}

__global__ void __launch_bounds__(256, 1)
gemm_o_tc(float* __restrict__ out) {
    gemm_tc<3>(g_ahi, g_alo, g_whi + 3u*WN, g_wlo + 3u*WN, out);
}

/* ============== flash attention on mma.sync (3-term bf16 split) ==========
   CTA: (qt, bh) -> 64 q rows x full window; 4 warps x m16.
   K tiles: ldmatrix (k-major, like GEMM B).  V tiles: ldmatrix.trans.
   P reused register-resident via C-frag -> A-frag identity.               */
#define AST   144                     /* bytes per smem row (72 shorts)   */
#define ATILE (64 * AST)              /* 9216 per component tile          */
#define ASM_ST (2 * ATILE)            /* after Qh, Ql                     */
#define ATT_SMEM (ASM_ST + 8 * ATILE) /* 92160                            */

__device__ __forceinline__ void attn_stage(unsigned sb, int s, int bh, int kt, int tid) {
    unsigned st = sb + ASM_ST + s * (4 * ATILE);
#pragma unroll
    for (int i = 0; i < 4; i++) {
        int op = tid + i * 128;               /* 0..511 */
        int r = op >> 3, seg = op & 7;
        size_t src = ((size_t)bh * SWIN + kt * 64 + r) * HDIM + seg * 8;
        unsigned d = st + r * AST + seg * 16;
        cpa16(d,             g_khi + src);
        cpa16(d + ATILE,     g_klo + src);
        cpa16(d + 2 * ATILE, g_vhi + src);
        cpa16(d + 3 * ATILE, g_vlo + src);
    }
}

__global__ void __launch_bounds__(128, 2) attn_kernel() {
    extern __shared__ char sm[];
    unsigned sb = s2u(sm);
    int qt = blockIdx.x, bh = blockIdx.y;
    int tid = threadIdx.x, w = tid >> 5, lane = tid & 31;

    /* Q hi/lo -> smem, plus first K/V stage */
#pragma unroll
    for (int i = 0; i < 4; i++) {
        int op = tid + i * 128;
        int r = op >> 3, seg = op & 7;
        size_t src = ((size_t)bh * SEQT + qt * 64 + r) * HDIM + seg * 8;
        unsigned d = sb + r * AST + seg * 16;
        cpa16(d,         g_qhi + src);
        cpa16(d + ATILE, g_qlo + src);
    }
    attn_stage(sb, 0, bh, 0, tid);
    cp_commit();
    attn_stage(sb, 1, bh, 1, tid);
    cp_commit();
    cp_wait1();
    __syncthreads();

    /* Q fragments (persistent) */
    unsigned aqh[4][4], aql[4][4];
    unsigned aoff = (w * 16 + (lane & 15)) * AST + ((lane >> 4) << 4);
#pragma unroll
    for (int ks = 0; ks < 4; ks++) {
        ldmx4(aqh[ks], sb + aoff + ks * 32);
        ldmx4(aql[ks], sb + ATILE + aoff + ks * 32);
    }

    unsigned boffK = ((((lane >> 4) << 3) + (lane & 7))) * AST + (((lane >> 3) & 1) << 4);
    unsigned voff  = ((lane & 7) + (((lane >> 3) & 1) << 3)) * AST + ((lane >> 4) << 4);

    float acc[8][4];
#pragma unroll
    for (int dt = 0; dt < 8; dt++)
#pragma unroll
        for (int q = 0; q < 4; q++) acc[dt][q] = 0.f;
    float mrow[2] = {-1e30f, -1e30f}, lrow[2] = {0.f, 0.f};

    int ktmax = qt + 4;
    for (int kt = 0; kt <= ktmax; kt++) {
        int cur = kt & 1;
        cp_wait1();
        __syncthreads();
        unsigned stK = sb + ASM_ST + cur * (4 * ATILE);
        unsigned stV = stK + 2 * ATILE;

        /* ---- scores = Q @ K^T (3-term) ---- */
        float sc[8][4];
#pragma unroll
        for (int j = 0; j < 8; j++)
#pragma unroll
            for (int q = 0; q < 4; q++) sc[j][q] = 0.f;
#pragma unroll
        for (int ks = 0; ks < 4; ks++) {
#pragma unroll
            for (int np = 0; np < 4; np++) {
                unsigned kh[4], kl[4];
                unsigned a = stK + boffK + np * (16 * AST) + ks * 32;
                ldmx4(kh, a);
                ldmx4(kl, a + ATILE);
                mma_bf16(sc[2*np],   aqh[ks], kh[0], kh[1]);
                mma_bf16(sc[2*np+1], aqh[ks], kh[2], kh[3]);
                mma_bf16(sc[2*np],   aqh[ks], kl[0], kl[1]);
                mma_bf16(sc[2*np+1], aqh[ks], kl[2], kl[3]);
                mma_bf16(sc[2*np],   aql[ks], kh[0], kh[1]);
                mma_bf16(sc[2*np+1], aql[ks], kh[2], kh[3]);
            }
        }
        /* diagonal mask */
        if (kt == ktmax) {
#pragma unroll
            for (int j = 0; j < 8; j++)
#pragma unroll
                for (int q = 0; q < 4; q++) {
                    int col = j * 8 + (lane & 3) * 2 + (q & 1);
                    int row = w * 16 + (lane >> 2) + (q >> 1) * 8;
                    if (col > row) sc[j][q] = -1e30f;
                }
        }
        /* ---- online softmax (two row-halves per thread) ---- */
#pragma unroll
        for (int h = 0; h < 2; h++) {
            float mx = -1e30f;
#pragma unroll
            for (int j = 0; j < 8; j++)
                mx = fmaxf(mx, fmaxf(sc[j][2*h], sc[j][2*h+1]));
            mx = fmaxf(mx, __shfl_xor_sync(0xffffffffu, mx, 1));
            mx = fmaxf(mx, __shfl_xor_sync(0xffffffffu, mx, 2));
            float mnew = fmaxf(mrow[h], mx);
            float fct  = __expf(mrow[h] - mnew);
            mrow[h] = mnew;
            float sum = 0.f;
#pragma unroll
            for (int j = 0; j < 8; j++) {
                float p0 = __expf(sc[j][2*h]   - mnew);
                float p1 = __expf(sc[j][2*h+1] - mnew);
                sc[j][2*h] = p0; sc[j][2*h+1] = p1;
                sum += p0 + p1;
            }
            sum += __shfl_xor_sync(0xffffffffu, sum, 1);
            sum += __shfl_xor_sync(0xffffffffu, sum, 2);
            lrow[h] = lrow[h] * fct + sum;
#pragma unroll
            for (int dt = 0; dt < 8; dt++) {
                acc[dt][2*h]   *= fct;
                acc[dt][2*h+1] *= fct;
            }
        }
        /* ---- acc += P @ V (3-term); P frags from score C-frags ---- */
#pragma unroll
        for (int kp = 0; kp < 4; kp++) {
            unsigned aph[4], apl[4];
            aph[0] = pack2(sc[2*kp][0],   sc[2*kp][1]);
            aph[1] = pack2(sc[2*kp][2],   sc[2*kp][3]);
            aph[2] = pack2(sc[2*kp+1][0], sc[2*kp+1][1]);
            aph[3] = pack2(sc[2*kp+1][2], sc[2*kp+1][3]);
            apl[0] = pack2lo(sc[2*kp][0],   sc[2*kp][1],   aph[0]);
            apl[1] = pack2lo(sc[2*kp][2],   sc[2*kp][3],   aph[1]);
            apl[2] = pack2lo(sc[2*kp+1][0], sc[2*kp+1][1], aph[2]);
            apl[3] = pack2lo(sc[2*kp+1][2], sc[2*kp+1][3], aph[3]);
#pragma unroll
            for (int dd = 0; dd < 4; dd++) {
                unsigned vh[4], vl[4];
                unsigned a = stV + voff + kp * (16 * AST) + dd * 32;
                ldmx4t(vh, a);
                ldmx4t(vl, a + ATILE);
                mma_bf16(acc[2*dd],   aph, vh[0], vh[1]);
                mma_bf16(acc[2*dd+1], aph, vh[2], vh[3]);
                mma_bf16(acc[2*dd],   aph, vl[0], vl[1]);
                mma_bf16(acc[2*dd+1], aph, vl[2], vl[3]);
                mma_bf16(acc[2*dd],   apl, vh[0], vh[1]);
                mma_bf16(acc[2*dd+1], apl, vh[2], vh[3]);
            }
        }
        __syncthreads();
        if (kt + 2 <= ktmax) attn_stage(sb, cur, bh, kt + 2, tid);
        cp_commit();
    }

    /* ---- epilogue: normalize, bf16 split -> g_ahi/alo ---- */
    int b = bh >> 5, hh = bh & 31;
#pragma unroll
    for (int h = 0; h < 2; h++) {
        int t = qt * 64 + w * 16 + (lane >> 2) + h * 8;
        float inv = 1.f / lrow[h];
#pragma unroll
        for (int dt = 0; dt < 8; dt++) {
            float o0 = acc[dt][2*h] * inv, o1 = acc[dt][2*h+1] * inv;
            size_t idx = ((size_t)(b * SEQT + t)) * MDIM + hh * HDIM
                       + dt * 8 + (lane & 3) * 2;
            unsigned hp = pack2(o0, o1);
            *(unsigned*)(g_ahi + idx) = hp;
            *(unsigned*)(g_alo + idx) = pack2lo(o0, o1, hp);
        }
    }
}

/* ---------------- launch -------------------------------------------------- */
extern "C" void kernel_launch(void* const* d_in, const int* in_sizes, int n_in,
                              void* d_out, int out_size) {
    (void)in_sizes; (void)n_in; (void)out_size;
    const float* x  = (const float*)d_in[0];
    const float* pk = (const float*)d_in[1];
    const float* pv = (const float*)d_in[2];
    const float* Wq = (const float*)d_in[3];
    const float* Wk = (const float*)d_in[4];
    const float* Wv = (const float*)d_in[5];
    const float* Wo = (const float*)d_in[6];
    const int*  pos = (const int*)d_in[7];

    float* out = (float*)d_out;
    float* nk  = out + (size_t)MROWS * MDIM;
    float* nv  = nk + (size_t)BATCH * NHEAD * SWIN * HDIM;

    cudaFuncSetAttribute(attn_kernel,
                         cudaFuncAttributeMaxDynamicSharedMemorySize, ATT_SMEM);
    cudaFuncSetAttribute(gemm_qkv_tc,
                         cudaFuncAttributeMaxDynamicSharedMemorySize, GSMEM);
    cudaFuncSetAttribute(gemm_o_tc,
                         cudaFuncAttributeMaxDynamicSharedMemorySize, GSMEM);

    rope_table_kernel<<<32, 256>>>(pos);
    convert_kernel<<<(XN + 4 * WN) / 4 / 256, 256>>>(x, Wq, Wk, Wv, Wo);
    copy_cache_kernel<<<(2 * (1 << 21)) / 256, 256>>>(
        (const float4*)pk, (const float4*)pv, (float4*)nk, (float4*)nv);
    gemm_qkv_tc<<<dim3(MDIM / 128, MROWS / 128, 3), 256, GSMEM>>>(nk, nv);
    attn_kernel<<<dim3(4, BATCH * NHEAD), 128, ATT_SMEM>>>();
    gemm_o_tc<<<dim3(MDIM / 128, MROWS / 128, 1), 256, GSMEM>>>(out);
}